// round 16
// baseline (speedup 1.0000x reference)
#include <cuda_runtime.h>
#include <math.h>

// Problem constants
#define NB   64      // batch N
#define TT   1024    // time steps
#define DD   512     // input dim
#define HHD  512     // hidden dim
#define FH   2048    // 4*H

// Grouping: 4 independent groups x 32 CTAs; each group owns 16 batch rows and
// holds ALL of Wh in its combined smem (128KB/CTA). No cross-group sync.
#define NGRP   4
#define GCTA   32                        // CTAs per group
#define GROWS  (NB / NGRP)               // 16 batch rows per group

// GEMM/recurrence overlap: xw produced in 8 chunks of 128 t; per chunk,
// 32 (bx) x 64 (n) x 2 (tsub) = 4096 tiles signal a release-counter.
#define NCHUNK      8
#define TILES_PER_CHUNK 4096

// ---------------- device scratch (allocation-free rule: __device__ globals) ----
__device__ __align__(16) float g_xw[NB * TT * FH];   // xW+b, layout (t, n, col)
__device__ __align__(16) float g_WhT[FH * HHD];      // Wh transposed: (2048, 512)
__device__ __align__(16) float g_h[2][NB * HHD];     // double-buffered hidden state
__device__ __align__(128) unsigned g_gcnt[NGRP * 32];    // per-group barrier ctrs
__device__ __align__(128) unsigned g_cchunk[NCHUNK * 32]; // per-chunk ready ctrs

// packed fp32x2 ops (sm_100+)
__device__ __forceinline__ void ffma2(unsigned long long& d,
                                      unsigned long long a,
                                      unsigned long long b) {
    asm("fma.rn.f32x2 %0, %1, %2, %0;" : "+l"(d) : "l"(a), "l"(b));
}
__device__ __forceinline__ unsigned long long pack2(float x) {
    unsigned long long r;
    asm("mov.b64 %0, {%1, %1};" : "=l"(r) : "f"(x));
    return r;
}

// MUFU-based activations (EX2 + RCP), ~1e-6 accuracy, saturate cleanly.
__device__ __forceinline__ float fsig(float x) {
    return __fdividef(1.f, 1.f + __expf(-x));
}
__device__ __forceinline__ float ftanhf(float x) {
    return 1.f - __fdividef(2.f, __expf(2.f * x) + 1.f);
}

// ---------------- init: reset all counters + load h0 --------------------------
__global__ void init_kernel(const float* __restrict__ h0) {
    int i = blockIdx.x * blockDim.x + threadIdx.x;
    if (i < NGRP * 32) g_gcnt[i] = 0u;
    if (i < NCHUNK * 32) g_cchunk[i] = 0u;
    if (i < NB * HHD) g_h[0][i] = h0[i];
}

// ---------------- transpose Wh (512,2048) -> WhT (2048,512) -------------------
__global__ void transpose_wh(const float* __restrict__ Wh) {
    int idx = blockIdx.x * blockDim.x + threadIdx.x;   // coalesced read
    int k = idx >> 11;
    int col = idx & 2047;
    g_WhT[col * HHD + k] = Wh[idx];
}

// ---------------- phase 1: xW = X @ Wx + b, chunk-ordered, co-resident --------
// 64x64 tile, BK=8, 128 threads, ~60 regs, 4KB smem — sized to co-reside with
// the persistent lstm CTAs (which leave ~62KB smem / ~30K regs free per SM).
// blockIdx.y = c*128 + n*2 + tsub  (chunk-major launch order so chunk 0 tiles
// run first). After stores: bar + release-RED on the chunk counter.
__global__ __launch_bounds__(128, 2)
void gemm_xw(const float* __restrict__ X, const float* __restrict__ Wx,
             const float* __restrict__ bias) {
    __shared__ __align__(16) float As[8][64];
    __shared__ __align__(16) float Bs[8][64];

    const int tid  = threadIdx.x;
    const int c    = blockIdx.y >> 7;         // chunk 0..7
    const int n    = (blockIdx.y >> 1) & 63;  // batch row
    const int tsub = blockIdx.y & 1;          // 64-t half of the chunk
    const int row0 = n * 1024 + c * 128 + tsub * 64;  // m = n*1024 + t
    const int col0 = blockIdx.x * 64;

    const int aRow = tid >> 1;            // 0..63
    const int aCol = (tid & 1) * 4;       // 0 or 4
    const int bRow = tid >> 4;            // 0..7
    const int bCol = (tid & 15) * 4;      // 0..60
    const int ty   = tid >> 3;            // 0..15 -> rows ty*4..+3
    const int tx   = tid & 7;             // cols tx*8..+7

    const float* Ap = X  + (size_t)(row0 + aRow) * DD + aCol;
    const float* Bp = Wx + (size_t)bRow * FH + col0 + bCol;

    unsigned long long acc[4][4];         // 4 rows x 8 cols (4 packed pairs)
#pragma unroll
    for (int i = 0; i < 4; i++)
#pragma unroll
        for (int p = 0; p < 4; p++) acc[i][p] = 0ull;

    for (int k0 = 0; k0 < DD; k0 += 8) {
        float4 av = __ldg((const float4*)(Ap + k0));
        float4 bv = __ldg((const float4*)(Bp + (size_t)k0 * FH));
        As[aCol + 0][aRow] = av.x;
        As[aCol + 1][aRow] = av.y;
        As[aCol + 2][aRow] = av.z;
        As[aCol + 3][aRow] = av.w;
        *(float4*)&Bs[bRow][bCol] = bv;
        __syncthreads();
#pragma unroll
        for (int k = 0; k < 8; k++) {
            float4 a4 = *(const float4*)&As[k][ty * 4];
            ulonglong2 b0 = *(const ulonglong2*)&Bs[k][tx * 8];
            ulonglong2 b1 = *(const ulonglong2*)&Bs[k][tx * 8 + 4];
            float ar[4] = {a4.x, a4.y, a4.z, a4.w};
#pragma unroll
            for (int i = 0; i < 4; i++) {
                unsigned long long aa = pack2(ar[i]);
                ffma2(acc[i][0], aa, b0.x);
                ffma2(acc[i][1], aa, b0.y);
                ffma2(acc[i][2], aa, b1.x);
                ffma2(acc[i][3], aa, b1.y);
            }
        }
        __syncthreads();
    }

    float4 bb0 = __ldg((const float4*)&bias[col0 + tx * 8]);
    float4 bb1 = __ldg((const float4*)&bias[col0 + tx * 8 + 4]);
#pragma unroll
    for (int i = 0; i < 4; i++) {
        int m  = row0 + ty * 4 + i;
        int tt = m & (TT - 1);
        int nn = m >> 10;
        float* orow = g_xw + ((size_t)(tt * NB + nn)) * FH + col0 + tx * 8;
        union { unsigned long long u; float2 f; } p0, p1, p2, p3;
        p0.u = acc[i][0]; p1.u = acc[i][1];
        p2.u = acc[i][2]; p3.u = acc[i][3];
        *(float4*)(orow)     = make_float4(p0.f.x + bb0.x, p0.f.y + bb0.y,
                                           p1.f.x + bb0.z, p1.f.y + bb0.w);
        *(float4*)(orow + 4) = make_float4(p2.f.x + bb1.x, p2.f.y + bb1.y,
                                           p3.f.x + bb1.z, p3.f.y + bb1.w);
    }

    // signal: all tile stores -> bar -> gpu-scope release RED on chunk counter
    __syncthreads();
    if (tid == 0) {
        asm volatile("red.release.gpu.add.u32 [%0], 1;"
                     :: "l"(&g_cchunk[c * 32]) : "memory");
    }
}

// ---------------- phase 2: group-local persistent LSTM recurrence -------------
// Identical to R15 (proven: 10.83ms, rel_err 2.5e-7) except the per-chunk
// acquire gate on g_cchunk before consuming each 128-step slab of xw.
#define HSTRIDE 516                               // 512 + 4 pad
#define HT_F    (GROWS * HSTRIDE)                 // 8256 floats (h tile)
#define WT_F    (64 * HSTRIDE)                    // 33024 floats (W tile)
#define LSTM_SMEM_BYTES ((HT_F + WT_F) * 4)       // 165,120 B

__global__ __launch_bounds__(256, 1)
void lstm_kernel(float* __restrict__ out) {
    extern __shared__ float sm[];
    float* sh = sm;               // h tile [16][516]
    float* sw = sm + HT_F;        // W tile [64][516], row = gate*16 + jc

    const int tid = threadIdx.x;
    const int jc  = tid >> 4;          // column within CTA's 16 (0..15)
    const int r   = tid & 15;          // group-local batch row (0..15)
    const int g   = blockIdx.x >> 5;   // group id 0..3
    const int m   = blockIdx.x & 31;   // member id 0..31
    const int c0  = m * 16;            // first gate-local column
    const int j   = c0 + jc;           // gate-local column 0..511
    const int n   = g * GROWS + r;     // global batch row

    unsigned* gcnt = &g_gcnt[g * 32];  // group-private counter (128B apart)

    // ---- stage W slice once: smem row rw = gate*16 + jc' ----
    for (int i = tid; i < 8192; i += 256) {        // 64 rows x 128 float4
        int rw = i >> 7;
        int kq = (i & 127) * 4;
        int G  = (rw >> 4) * HHD + c0 + (rw & 15); // WhT row (a-column)
        float4 v = __ldg((const float4*)&g_WhT[(size_t)G * HHD + kq]);
        *(float4*)&sw[rw * HSTRIDE + kq] = v;
    }
    __syncthreads();

    const ulonglong2* wp0 = (const ulonglong2*)(sw + (0 * 16 + jc) * HSTRIDE);
    const ulonglong2* wp1 = (const ulonglong2*)(sw + (1 * 16 + jc) * HSTRIDE);
    const ulonglong2* wp2 = (const ulonglong2*)(sw + (2 * 16 + jc) * HSTRIDE);
    const ulonglong2* wp3 = (const ulonglong2*)(sw + (3 * 16 + jc) * HSTRIDE);
    const ulonglong2* hq  = (const ulonglong2*)(sh + r * HSTRIDE);

    float c = 0.f;
    int nb = 0;

    for (int t = 0; t < TT; t++) {
        // ---- chunk gate: wait until gemm finished this 128-step slab ----
        if ((t & 127) == 0) {
            if (tid == 0) {
                const unsigned* cc = &g_cchunk[(t >> 7) * 32];
                unsigned v;
                do {
                    asm volatile("ld.acquire.gpu.u32 %0, [%1];"
                                 : "=r"(v) : "l"(cc) : "memory");
                    if (v >= TILES_PER_CHUNK) break;
                    __nanosleep(256);
                } while (true);
            }
            __syncthreads();
        }

        // xW prefetch (consumed at step end)
        const size_t xb = ((size_t)(t * NB + n)) * FH + j;
        float xw0 = __ldg(&g_xw[xb]);
        float xw1 = __ldg(&g_xw[xb + 512]);
        float xw2 = __ldg(&g_xw[xb + 1024]);
        float xw3 = __ldg(&g_xw[xb + 1536]);

        // ---- stage group's h (32KB) into smem: 8 coalesced ld.cg/thread ----
        const float* hsrc = g_h[nb] + (size_t)g * GROWS * HHD;
#pragma unroll
        for (int u = 0; u < 8; u++) {
            int i = tid + u * 256;                    // float4 index 0..2047
            float4 v = __ldcg((const float4*)&hsrc[i * 4]);
            *(float4*)&sh[(i >> 7) * HSTRIDE + (i & 127) * 4] = v;
        }
        __syncthreads();

        // ---- full-k dot: 5 LDS.128 + 8 FFMA2 per 4k, 128 iters ----
        unsigned long long a0 = 0ull, a1 = 0ull, a2 = 0ull, a3 = 0ull;
#pragma unroll 8
        for (int kq = 0; kq < HHD / 4; kq++) {
            ulonglong2 hv = hq[kq];
            ulonglong2 v0 = wp0[kq];
            ulonglong2 v1 = wp1[kq];
            ulonglong2 v2 = wp2[kq];
            ulonglong2 v3 = wp3[kq];
            ffma2(a0, hv.x, v0.x); ffma2(a0, hv.y, v0.y);
            ffma2(a1, hv.x, v1.x); ffma2(a1, hv.y, v1.y);
            ffma2(a2, hv.x, v2.x); ffma2(a2, hv.y, v2.y);
            ffma2(a3, hv.x, v3.x); ffma2(a3, hv.y, v3.y);
        }
        union { unsigned long long u; float2 f; } u0, u1, u2, u3;
        u0.u = a0; u1.u = a1; u2.u = a2; u3.u = a3;

        // gates (split order [i, f, o, g]) — proven math
        float ai = xw0 + u0.f.x + u0.f.y;
        float af = xw1 + u1.f.x + u1.f.y;
        float ao = xw2 + u2.f.x + u2.f.y;
        float ag = xw3 + u3.f.x + u3.f.y;
        float ig = fsig(ai);
        float fg = fsig(af);
        float og = fsig(ao);
        float gg = ftanhf(ag);
        c = fg * c + ig * gg;
        float hn = og * ftanhf(c);

        out[((size_t)n * TT + t) * HHD + j] = hn;
        g_h[nb ^ 1][(size_t)n * HHD + j] = hn;

        // ---- group-local barrier: bar -> release-RED -> acquire spin -> bar --
        __syncthreads();
        if (tid == 0) {
            asm volatile("red.release.gpu.add.u32 [%0], 1;"
                         :: "l"(gcnt) : "memory");
            unsigned tgt = (unsigned)(t + 1) * (unsigned)GCTA;
            unsigned v;
            do {
                asm volatile("ld.acquire.gpu.u32 %0, [%1];"
                             : "=r"(v) : "l"(gcnt) : "memory");
                if (v >= tgt) break;
                __nanosleep(32);
            } while (true);
        }
        __syncthreads();
        nb ^= 1;
    }
}

// ---------------- launch: forked-graph concurrent gemm + lstm -----------------
extern "C" void kernel_launch(void* const* d_in, const int* in_sizes, int n_in,
                              void* d_out, int out_size) {
    (void)in_sizes; (void)n_in; (void)out_size;
    const float* x  = (const float*)d_in[0];   // (64,1024,512)
    const float* h0 = (const float*)d_in[1];   // (64,512)
    const float* Wx = (const float*)d_in[2];   // (512,2048)
    const float* Wh = (const float*)d_in[3];   // (512,2048)
    const float* b  = (const float*)d_in[4];   // (2048)
    float* out = (float*)d_out;                // (64,1024,512) fp32

    // host-side objects, created once on the (non-captured) correctness call
    static cudaStream_t s2 = nullptr;
    static cudaEvent_t evA = nullptr, evB = nullptr;
    if (s2 == nullptr) {
        cudaStreamCreateWithFlags(&s2, cudaStreamNonBlocking);
        cudaEventCreateWithFlags(&evA, cudaEventDisableTiming);
        cudaEventCreateWithFlags(&evB, cudaEventDisableTiming);
        cudaFuncSetAttribute(lstm_kernel,
                             cudaFuncAttributeMaxDynamicSharedMemorySize,
                             LSTM_SMEM_BYTES);
    }

    init_kernel<<<128, 256>>>(h0);               // counters + h0
    transpose_wh<<<(DD * FH) / 256, 256>>>(Wh);  // WhT

    // fork: gemm runs concurrently with the persistent recurrence
    cudaEventRecord(evA, 0);
    cudaStreamWaitEvent(s2, evA, 0);
    gemm_xw<<<dim3(32, 1024), 128, 0, s2>>>(x, Wx, b);
    cudaEventRecord(evB, s2);

    lstm_kernel<<<128, 256, LSTM_SMEM_BYTES>>>(out);

    // join: graph end state includes the gemm branch
    cudaStreamWaitEvent(0, evB, 0);
}

// round 17
// speedup vs baseline: 1.2155x; 1.2155x over previous
#include <cuda_runtime.h>
#include <math.h>

// Problem constants
#define NB   64      // batch N
#define TT   1024    // time steps
#define DD   512     // input dim
#define HHD  512     // hidden dim
#define FH   2048    // 4*H

// Grouping: 4 independent groups x 32 CTAs; each group owns 16 batch rows and
// holds ALL of Wh in its combined smem (128KB/CTA). No cross-group sync.
#define NGRP   4
#define GCTA   32                        // CTAs per group
#define GROWS  (NB / NGRP)               // 16 batch rows per group

// ---------------- device scratch (allocation-free rule: __device__ globals) ----
__device__ __align__(16) float g_xw[NB * TT * FH];   // xW+b, layout (t, n, col)
__device__ __align__(16) float g_WhT[FH * HHD];      // Wh transposed: (2048, 512)
__device__ __align__(16) float g_h[2][NB * HHD];     // double-buffered hidden state
__device__ __align__(128) unsigned g_gcnt[NGRP * 32]; // per-group barrier ctrs

// packed fp32x2 ops (sm_100+)
__device__ __forceinline__ void ffma2(unsigned long long& d,
                                      unsigned long long a,
                                      unsigned long long b) {
    asm("fma.rn.f32x2 %0, %1, %2, %0;" : "+l"(d) : "l"(a), "l"(b));
}
__device__ __forceinline__ void fadd2(unsigned long long& d,
                                      unsigned long long a) {
    asm("add.rn.f32x2 %0, %0, %1;" : "+l"(d) : "l"(a));
}
__device__ __forceinline__ unsigned long long pack2(float x) {
    unsigned long long r;
    asm("mov.b64 %0, {%1, %1};" : "=l"(r) : "f"(x));
    return r;
}

// MUFU-based activations (EX2 + RCP), ~1e-6 accuracy, saturate cleanly.
__device__ __forceinline__ float fsig(float x) {
    return __fdividef(1.f, 1.f + __expf(-x));
}
__device__ __forceinline__ float ftanhf(float x) {
    return 1.f - __fdividef(2.f, __expf(2.f * x) + 1.f);
}

// ---------------- init: reset barrier counters + load h0 ----------------------
__global__ void init_kernel(const float* __restrict__ h0) {
    int i = blockIdx.x * blockDim.x + threadIdx.x;
    if (i < NGRP * 32) g_gcnt[i] = 0u;
    if (i < NB * HHD) g_h[0][i] = h0[i];
}

// ---------------- transpose Wh (512,2048) -> WhT (2048,512) -------------------
__global__ void transpose_wh(const float* __restrict__ Wh) {
    int idx = blockIdx.x * blockDim.x + threadIdx.x;   // coalesced read
    int k = idx >> 11;
    int col = idx & 2047;
    g_WhT[col * HHD + k] = Wh[idx];
}

// ---------------- phase 1: xW = X @ Wx + b  (65536x2048x512 SGEMM) ------------
// (byte-identical to R15's proven version: 128x128 tile, BK=8, 256 thr, FFMA2)
__global__ __launch_bounds__(256, 2)
void gemm_xw(const float* __restrict__ X, const float* __restrict__ Wx,
             const float* __restrict__ bias) {
    __shared__ __align__(16) float As[8][128];
    __shared__ __align__(16) float Bs[8][128];

    const int tid  = threadIdx.x;
    const int row0 = blockIdx.y * 128;
    const int col0 = blockIdx.x * 128;

    const int aRow = tid >> 1;
    const int aCol = (tid & 1) * 4;
    const int bRow = tid >> 5;
    const int bCol = (tid & 31) * 4;

    const int tx = tid & 15;
    const int ty = tid >> 4;

    const float* Ap = X  + (size_t)(row0 + aRow) * DD + aCol;
    const float* Bp = Wx + (size_t)bRow * FH + col0 + bCol;

    unsigned long long acc2[8][4];
#pragma unroll
    for (int i = 0; i < 8; i++)
#pragma unroll
        for (int p = 0; p < 4; p++) acc2[i][p] = 0ull;

    for (int k0 = 0; k0 < DD; k0 += 8) {
        float4 av = __ldg((const float4*)(Ap + k0));
        float4 bv = __ldg((const float4*)(Bp + (size_t)k0 * FH));
        As[aCol + 0][aRow] = av.x;
        As[aCol + 1][aRow] = av.y;
        As[aCol + 2][aRow] = av.z;
        As[aCol + 3][aRow] = av.w;
        *(float4*)&Bs[bRow][bCol] = bv;
        __syncthreads();
#pragma unroll
        for (int k = 0; k < 8; k++) {
            float4 a0 = *(const float4*)&As[k][ty * 8];
            float4 a1 = *(const float4*)&As[k][ty * 8 + 4];
            ulonglong2 bp0 = *(const ulonglong2*)&Bs[k][tx * 4];
            ulonglong2 bp1 = *(const ulonglong2*)&Bs[k][64 + tx * 4];
            float ar[8] = {a0.x, a0.y, a0.z, a0.w, a1.x, a1.y, a1.z, a1.w};
#pragma unroll
            for (int i = 0; i < 8; i++) {
                unsigned long long aa = pack2(ar[i]);
                ffma2(acc2[i][0], aa, bp0.x);
                ffma2(acc2[i][1], aa, bp0.y);
                ffma2(acc2[i][2], aa, bp1.x);
                ffma2(acc2[i][3], aa, bp1.y);
            }
        }
        __syncthreads();
    }

    float4 bb0 = __ldg((const float4*)&bias[col0 + tx * 4]);
    float4 bb1 = __ldg((const float4*)&bias[col0 + 64 + tx * 4]);
#pragma unroll
    for (int i = 0; i < 8; i++) {
        int m  = row0 + ty * 8 + i;
        int tt = m & (TT - 1);
        int nn = m >> 10;
        float* orow = g_xw + ((size_t)(tt * NB + nn)) * FH + col0;
        union { unsigned long long u; float2 f; } p0, p1, p2, p3;
        p0.u = acc2[i][0]; p1.u = acc2[i][1];
        p2.u = acc2[i][2]; p3.u = acc2[i][3];
        float4 v0 = make_float4(p0.f.x + bb0.x, p0.f.y + bb0.y,
                                p1.f.x + bb0.z, p1.f.y + bb0.w);
        float4 v1 = make_float4(p2.f.x + bb1.x, p2.f.y + bb1.y,
                                p3.f.x + bb1.z, p3.f.y + bb1.w);
        *(float4*)(orow + tx * 4)      = v0;
        *(float4*)(orow + 64 + tx * 4) = v1;
    }
}

// ---------------- phase 2: group-local persistent LSTM recurrence -------------
// R15 structure (proven 10.83ms) + R12-proven 2-way k-split:
// 128 CTAs x 512 threads. group g = bid>>5 owns batch rows g*16..+15; member
// m = bid&31 owns gate-local cols c0 = m*16..+15 (W slice 128KB in smem).
// Logical thread (jc = (tid>>4)&15, r = tid&15) owns element (row g*16+r,
// col c0+jc); z = tid>>8 splits k in half. z=1 dumps 4 packed partials to an
// 8KB smem buffer; z=0 combines (add.rn.f32x2) and runs the R15-identical
// activation path + stores, and owns register cell c.
#define HSTRIDE 516                               // 512 + 4 pad
#define HT_F    (GROWS * HSTRIDE)                 // 8256 floats (h tile)
#define WT_F    (64 * HSTRIDE)                    // 33024 floats (W tile)
#define LSTM_SMEM_BYTES ((HT_F + WT_F) * 4 + 256 * 4 * 8)   // +8KB red = 173,312 B

__global__ __launch_bounds__(512, 1)
void lstm_kernel(float* __restrict__ out) {
    extern __shared__ float sm[];
    float* sh = sm;               // h tile [16][516]
    float* sw = sm + HT_F;        // W tile [64][516], row = gate*16 + jc
    unsigned long long* red = (unsigned long long*)(sm + HT_F + WT_F);

    const int tid = threadIdx.x;
    const int z   = tid >> 8;              // k-half (warps 0-7: z=0, 8-15: z=1)
    const int jc  = (tid >> 4) & 15;       // column within CTA's 16
    const int r   = tid & 15;              // group-local batch row
    const int g   = blockIdx.x >> 5;       // group id 0..3
    const int m   = blockIdx.x & 31;       // member id 0..31
    const int c0  = m * 16;                // first gate-local column
    const int j   = c0 + jc;               // gate-local column 0..511
    const int n   = g * GROWS + r;         // global batch row

    unsigned* gcnt = &g_gcnt[g * 32];      // group-private counter

    // ---- stage W slice once: smem row rw = gate*16 + jc' ----
    for (int i = tid; i < 8192; i += 512) {        // 64 rows x 128 float4
        int rw = i >> 7;
        int kq = (i & 127) * 4;
        int G  = (rw >> 4) * HHD + c0 + (rw & 15); // WhT row (a-column)
        float4 v = __ldg((const float4*)&g_WhT[(size_t)G * HHD + kq]);
        *(float4*)&sw[rw * HSTRIDE + kq] = v;
    }
    __syncthreads();

    // per-thread pointers into own k-half (z*256 floats = z*64 ulonglong2)
    const ulonglong2* wp0 = (const ulonglong2*)(sw + (0 * 16 + jc) * HSTRIDE) + z * 64;
    const ulonglong2* wp1 = (const ulonglong2*)(sw + (1 * 16 + jc) * HSTRIDE) + z * 64;
    const ulonglong2* wp2 = (const ulonglong2*)(sw + (2 * 16 + jc) * HSTRIDE) + z * 64;
    const ulonglong2* wp3 = (const ulonglong2*)(sw + (3 * 16 + jc) * HSTRIDE) + z * 64;
    const ulonglong2* hq  = (const ulonglong2*)(sh + r * HSTRIDE) + z * 64;

    float c = 0.f;
    int nb = 0;

    for (int t = 0; t < TT; t++) {
        // xW prefetch (activation half only; consumed at step end)
        float xw0 = 0.f, xw1 = 0.f, xw2 = 0.f, xw3 = 0.f;
        if (z == 0) {
            const size_t xb = ((size_t)(t * NB + n)) * FH + j;
            xw0 = __ldg(&g_xw[xb]);
            xw1 = __ldg(&g_xw[xb + 512]);
            xw2 = __ldg(&g_xw[xb + 1024]);
            xw3 = __ldg(&g_xw[xb + 1536]);
        }

        // ---- stage group's h (32KB) into smem: 4 coalesced ld.cg/thread ----
        const float* hsrc = g_h[nb] + (size_t)g * GROWS * HHD;
#pragma unroll
        for (int u = 0; u < 4; u++) {
            int i = tid + u * 512;                    // float4 index 0..2047
            float4 v = __ldcg((const float4*)&hsrc[i * 4]);
            *(float4*)&sh[(i >> 7) * HSTRIDE + (i & 127) * 4] = v;
        }
        __syncthreads();

        // ---- half-k dot: 5 LDS.128 + 8 FFMA2 per 4k, 64 iters ----
        unsigned long long a0 = 0ull, a1 = 0ull, a2 = 0ull, a3 = 0ull;
#pragma unroll 8
        for (int kq = 0; kq < 64; kq++) {
            ulonglong2 hv = hq[kq];
            ulonglong2 v0 = wp0[kq];
            ulonglong2 v1 = wp1[kq];
            ulonglong2 v2 = wp2[kq];
            ulonglong2 v3 = wp3[kq];
            ffma2(a0, hv.x, v0.x); ffma2(a0, hv.y, v0.y);
            ffma2(a1, hv.x, v1.x); ffma2(a1, hv.y, v1.y);
            ffma2(a2, hv.x, v2.x); ffma2(a2, hv.y, v2.y);
            ffma2(a3, hv.x, v3.x); ffma2(a3, hv.y, v3.y);
        }

        // ---- cross-half reduction (8KB smem region) ----
        if (z == 1) {
            ulonglong2* r2 = (ulonglong2*)(red + (tid & 255) * 4);
            r2[0] = make_ulonglong2(a0, a1);
            r2[1] = make_ulonglong2(a2, a3);
        }
        __syncthreads();

        if (z == 0) {
            const ulonglong2* r2 = (const ulonglong2*)(red + tid * 4);
            ulonglong2 p0 = r2[0], p1 = r2[1];
            fadd2(a0, p0.x); fadd2(a1, p0.y);
            fadd2(a2, p1.x); fadd2(a3, p1.y);

            union { unsigned long long u; float2 f; } u0, u1, u2, u3;
            u0.u = a0; u1.u = a1; u2.u = a2; u3.u = a3;

            // gates (split order [i, f, o, g]) — proven math
            float ai = xw0 + u0.f.x + u0.f.y;
            float af = xw1 + u1.f.x + u1.f.y;
            float ao = xw2 + u2.f.x + u2.f.y;
            float ag = xw3 + u3.f.x + u3.f.y;
            float ig = fsig(ai);
            float fg = fsig(af);
            float og = fsig(ao);
            float gg = ftanhf(ag);
            c = fg * c + ig * gg;
            float hn = og * ftanhf(c);

            out[((size_t)n * TT + t) * HHD + j] = hn;
            g_h[nb ^ 1][(size_t)n * HHD + j] = hn;
        }

        // ---- group-local barrier: bar -> release-RED -> acquire spin -> bar --
        __syncthreads();
        if (tid == 0) {
            asm volatile("red.release.gpu.add.u32 [%0], 1;"
                         :: "l"(gcnt) : "memory");
            unsigned tgt = (unsigned)(t + 1) * (unsigned)GCTA;
            unsigned v;
            do {
                asm volatile("ld.acquire.gpu.u32 %0, [%1];"
                             : "=r"(v) : "l"(gcnt) : "memory");
                if (v >= tgt) break;
                __nanosleep(32);
            } while (true);
        }
        __syncthreads();
        nb ^= 1;
    }
}

// ---------------- launch (serial, R15 structure) ------------------------------
extern "C" void kernel_launch(void* const* d_in, const int* in_sizes, int n_in,
                              void* d_out, int out_size) {
    (void)in_sizes; (void)n_in; (void)out_size;
    const float* x  = (const float*)d_in[0];   // (64,1024,512)
    const float* h0 = (const float*)d_in[1];   // (64,512)
    const float* Wx = (const float*)d_in[2];   // (512,2048)
    const float* Wh = (const float*)d_in[3];   // (512,2048)
    const float* b  = (const float*)d_in[4];   // (2048)
    float* out = (float*)d_out;                // (64,1024,512) fp32

    cudaFuncSetAttribute(lstm_kernel,
                         cudaFuncAttributeMaxDynamicSharedMemorySize,
                         LSTM_SMEM_BYTES);

    init_kernel<<<128, 256>>>(h0);
    transpose_wh<<<(DD * FH) / 256, 256>>>(Wh);
    gemm_xw<<<dim3(FH / 128, (NB * TT) / 128), 256>>>(x, Wx, b);
    lstm_kernel<<<128, 512, LSTM_SMEM_BYTES>>>(out);
}